// round 1
// baseline (speedup 1.0000x reference)
#include <cuda_runtime.h>
#include <math.h>

// Problem constants
#define S_LEN  2048
#define DMODEL 1024
#define NH     16
#define HD     64
#define BATCH  4
#define MROWS  (BATCH * S_LEN)   // 8192
#define N3     (3 * DMODEL)      // 3072

// Scratch (no allocation allowed -> device globals)
__device__ float g_qkv[(size_t)MROWS * N3];    // [m, 3*DMODEL] raw QKV, rope applied in-place
__device__ float g_ctx[(size_t)MROWS * DMODEL];// [m, DMODEL] attention context

// ---------------------------------------------------------------------------
// C[M,N] = A[M,K] @ W[N,K]^T   (both row-major, K contiguous)
// 128x128 block tile, BK=8, 256 threads, 8x8 per-thread micro-tile.
// M,N multiples of 128; K multiple of 8. (Holds for all our shapes.)
// ---------------------------------------------------------------------------
__global__ __launch_bounds__(256) void gemm_nt(const float* __restrict__ A,
                                               const float* __restrict__ W,
                                               float* __restrict__ C,
                                               int N, int K) {
    __shared__ float As[8][128];
    __shared__ float Bs[8][128];

    const int bm = blockIdx.y * 128;
    const int bn = blockIdx.x * 128;
    const int tid = threadIdx.x;

    const int lrow = tid >> 1;           // 0..127
    const int lcol = (tid & 1) * 4;      // 0 or 4
    const int tm = (tid >> 4) * 8;       // 0..120
    const int tn = (tid & 15) * 8;       // 0..120

    const float* Arow = A + (size_t)(bm + lrow) * K + lcol;
    const float* Wrow = W + (size_t)(bn + lrow) * K + lcol;

    float acc[8][8];
#pragma unroll
    for (int i = 0; i < 8; i++)
#pragma unroll
        for (int j = 0; j < 8; j++) acc[i][j] = 0.0f;

    for (int k0 = 0; k0 < K; k0 += 8) {
        float4 av = *(const float4*)(Arow + k0);
        float4 bv = *(const float4*)(Wrow + k0);
        __syncthreads();
        As[lcol + 0][lrow] = av.x; As[lcol + 1][lrow] = av.y;
        As[lcol + 2][lrow] = av.z; As[lcol + 3][lrow] = av.w;
        Bs[lcol + 0][lrow] = bv.x; Bs[lcol + 1][lrow] = bv.y;
        Bs[lcol + 2][lrow] = bv.z; Bs[lcol + 3][lrow] = bv.w;
        __syncthreads();
#pragma unroll
        for (int kk = 0; kk < 8; kk++) {
            float4 a0 = *(const float4*)&As[kk][tm];
            float4 a1 = *(const float4*)&As[kk][tm + 4];
            float4 b0 = *(const float4*)&Bs[kk][tn];
            float4 b1 = *(const float4*)&Bs[kk][tn + 4];
            float ar[8] = {a0.x, a0.y, a0.z, a0.w, a1.x, a1.y, a1.z, a1.w};
            float br[8] = {b0.x, b0.y, b0.z, b0.w, b1.x, b1.y, b1.z, b1.w};
#pragma unroll
            for (int i = 0; i < 8; i++)
#pragma unroll
                for (int j = 0; j < 8; j++) acc[i][j] += ar[i] * br[j];
        }
    }

#pragma unroll
    for (int i = 0; i < 8; i++) {
        float4* cp = (float4*)(C + (size_t)(bm + tm + i) * N + bn + tn);
        cp[0] = make_float4(acc[i][0], acc[i][1], acc[i][2], acc[i][3]);
        cp[1] = make_float4(acc[i][4], acc[i][5], acc[i][6], acc[i][7]);
    }
}

// ---------------------------------------------------------------------------
// RoPE in-place on the Q and K thirds of g_qkv.
// One thread per (m, h, j) pair; handles both q and k rotation.
// Mirrors reference fp32 math: freq = theta^(j/32); inv = 1/freq; ang = pos*inv
// ---------------------------------------------------------------------------
__global__ void rope_kernel(float* __restrict__ qkv, const int* __restrict__ pos_arr) {
    int idx = blockIdx.x * blockDim.x + threadIdx.x;
    const int total = MROWS * NH * (HD / 2);
    if (idx >= total) return;
    int j = idx & 31;
    int h = (idx >> 5) & (NH - 1);
    int m = idx >> 9;
    int s = m & (S_LEN - 1);
    int p = pos_arr[s];

    float freq = powf(10000.0f, (float)j * (1.0f / 32.0f));
    float inv = 1.0f / freq;
    float ang = (float)p * inv;
    float sn, cs;
    sincosf(ang, &sn, &cs);

    float* base = qkv + (size_t)m * N3 + h * HD + 2 * j;
    // q
    float q0 = base[0], q1 = base[1];
    base[0] = q0 * cs - q1 * sn;
    base[1] = q0 * sn + q1 * cs;
    // k (offset by DMODEL)
    float k0 = base[DMODEL], k1 = base[DMODEL + 1];
    base[DMODEL]     = k0 * cs - k1 * sn;
    base[DMODEL + 1] = k0 * sn + k1 * cs;
}

// ---------------------------------------------------------------------------
// Causal attention, online softmax (flash-style), fp32.
// Grid: (S/128, B*H). Block: 128 threads, one query per thread.
// K/V tiles of 32 keys staged through shared memory.
// Reads q,k,v from g_qkv strided layout; writes ctx [b,s, h*64+d].
// ---------------------------------------------------------------------------
#define QTILE 128
#define KTILE 32

__global__ __launch_bounds__(128) void attn_kernel(const float* __restrict__ qkv,
                                                   float* __restrict__ ctx) {
    const int qt = blockIdx.x;           // 0..15
    const int bh = blockIdx.y;           // 0..63
    const int b = bh >> 4;
    const int h = bh & 15;
    const int tid = threadIdx.x;
    const int sq = qt * QTILE + tid;

    const float* base = qkv + (size_t)b * S_LEN * N3 + h * HD;

    // load this thread's query row (rope already applied)
    float4 q[16];
    const float4* qrow = (const float4*)(base + (size_t)sq * N3);
#pragma unroll
    for (int i = 0; i < 16; i++) q[i] = qrow[i];

    float4 o[16];
#pragma unroll
    for (int i = 0; i < 16; i++) o[i] = make_float4(0.f, 0.f, 0.f, 0.f);
    float mx = -1e30f, lsum = 0.0f;

    __shared__ float Ks[KTILE * HD];
    __shared__ float Vs[KTILE * HD];

    const int nkt = qt * (QTILE / KTILE) + (QTILE / KTILE);  // causal tile count

    for (int kt = 0; kt < nkt; kt++) {
        const int k0 = kt * KTILE;
        __syncthreads();
        // stage K,V tiles: 512 float4 each, 128 threads -> 4 chunks per thread
#pragma unroll
        for (int c = tid; c < KTILE * HD / 4; c += 128) {
            int j = c >> 4;          // key within tile
            int d4 = c & 15;         // float4 within head dim
            const float* krow = base + (size_t)(k0 + j) * N3;
            ((float4*)Ks)[c] = ((const float4*)(krow + DMODEL))[d4];
            ((float4*)Vs)[c] = ((const float4*)(krow + 2 * DMODEL))[d4];
        }
        __syncthreads();

        // scores for 32 keys
        float sc[KTILE];
        float tmax = -1e30f;
#pragma unroll
        for (int j = 0; j < KTILE; j++) {
            const float4* kr = (const float4*)(Ks + j * HD);
            float s0 = 0.f, s1 = 0.f;
#pragma unroll
            for (int i = 0; i < 16; i += 2) {
                float4 kv0 = kr[i];
                float4 kv1 = kr[i + 1];
                s0 += q[i].x * kv0.x + q[i].y * kv0.y + q[i].z * kv0.z + q[i].w * kv0.w;
                s1 += q[i + 1].x * kv1.x + q[i + 1].y * kv1.y + q[i + 1].z * kv1.z + q[i + 1].w * kv1.w;
            }
            float s = (s0 + s1) * 0.125f;        // 1/sqrt(64)
            if (k0 + j > sq) s = -1e30f;         // causal mask
            sc[j] = s;
            tmax = fmaxf(tmax, s);
        }

        float mnew = fmaxf(mx, tmax);
        float corr = __expf(mx - mnew);
        lsum *= corr;
#pragma unroll
        for (int i = 0; i < 16; i++) {
            o[i].x *= corr; o[i].y *= corr; o[i].z *= corr; o[i].w *= corr;
        }
#pragma unroll
        for (int j = 0; j < KTILE; j++) {
            float p = __expf(sc[j] - mnew);
            lsum += p;
            const float4* vr = (const float4*)(Vs + j * HD);
#pragma unroll
            for (int i = 0; i < 16; i++) {
                float4 vv = vr[i];
                o[i].x += p * vv.x; o[i].y += p * vv.y;
                o[i].z += p * vv.z; o[i].w += p * vv.w;
            }
        }
        mx = mnew;
    }

    const float invl = 1.0f / lsum;
    float* crow = ctx + ((size_t)(b * S_LEN + sq)) * DMODEL + h * HD;
#pragma unroll
    for (int i = 0; i < 16; i++) {
        ((float4*)crow)[i] = make_float4(o[i].x * invl, o[i].y * invl,
                                         o[i].z * invl, o[i].w * invl);
    }
}

// ---------------------------------------------------------------------------
// Launch: QKV GEMM -> RoPE -> attention -> O GEMM
// ---------------------------------------------------------------------------
extern "C" void kernel_launch(void* const* d_in, const int* in_sizes, int n_in,
                              void* d_out, int out_size) {
    const float* x     = (const float*)d_in[0];   // [4,2048,1024]
    const int*   pos   = (const int*)d_in[1];     // [2048]
    const float* qkv_w = (const float*)d_in[2];   // [3072,1024]
    const float* o_w   = (const float*)d_in[3];   // [1024,1024]
    float* out = (float*)d_out;                   // [4,2048,1024]

    float *qkv_s = nullptr, *ctx_s = nullptr;
    cudaGetSymbolAddress((void**)&qkv_s, g_qkv);
    cudaGetSymbolAddress((void**)&ctx_s, g_ctx);

    // 1) fused QKV projection: [8192,3072] = x @ qkv_w^T
    {
        dim3 grid(N3 / 128, MROWS / 128);
        gemm_nt<<<grid, 256>>>(x, qkv_w, qkv_s, N3, DMODEL);
    }
    // 2) RoPE on q,k
    {
        int total = MROWS * NH * (HD / 2);
        rope_kernel<<<(total + 255) / 256, 256>>>(qkv_s, pos);
    }
    // 3) causal attention
    {
        dim3 grid(S_LEN / QTILE, BATCH * NH);
        attn_kernel<<<grid, 128>>>(qkv_s, ctx_s);
    }
    // 4) output projection: out = ctx @ o_w^T
    {
        dim3 grid(DMODEL / 128, MROWS / 128);
        gemm_nt<<<grid, 256>>>(ctx_s, o_w, out, DMODEL, DMODEL);
    }
}

// round 4
// speedup vs baseline: 1.2447x; 1.2447x over previous
#include <cuda_runtime.h>
#include <cuda_bf16.h>
#include <math.h>
#include <stdint.h>

// Problem constants
#define S_LEN  2048
#define DMODEL 1024
#define NH     16
#define HD     64
#define BATCH  4
#define MROWS  (BATCH * S_LEN)   // 8192
#define N3     (3 * DMODEL)      // 3072

// Scratch (no allocation allowed -> device globals)
__device__ float g_qkv[(size_t)MROWS * N3];      // [m, 3*DMODEL]
__device__ float g_ctx[(size_t)MROWS * DMODEL];  // [m, DMODEL]
__device__ __nv_bfloat16 g_ah[(size_t)MROWS * DMODEL];  // A hi (x or ctx)
__device__ __nv_bfloat16 g_al[(size_t)MROWS * DMODEL];  // A lo
__device__ __nv_bfloat16 g_bh[(size_t)N3 * DMODEL];     // W hi
__device__ __nv_bfloat16 g_bl[(size_t)N3 * DMODEL];     // W lo

// ---------------------------------------------------------------------------
// PTX helpers (portable: sm_80+ instructions only, no arch-'a' features)
// ---------------------------------------------------------------------------
__device__ __forceinline__ uint32_t smem_u32(const void* p) {
    uint32_t a;
    asm("{ .reg .u64 t; cvta.to.shared.u64 t, %1; cvt.u32.u64 %0, t; }" : "=r"(a) : "l"(p));
    return a;
}
__device__ __forceinline__ void cp_async16(uint32_t saddr, const void* gaddr) {
    asm volatile("cp.async.cg.shared.global [%0], [%1], 16;" :: "r"(saddr), "l"(gaddr));
}
__device__ __forceinline__ void ldsm_x4(uint32_t* r, uint32_t addr) {
    asm volatile("ldmatrix.sync.aligned.m8n8.x4.shared.b16 {%0,%1,%2,%3}, [%4];"
                 : "=r"(r[0]), "=r"(r[1]), "=r"(r[2]), "=r"(r[3]) : "r"(addr));
}
__device__ __forceinline__ void ldsm_x2(uint32_t* r, uint32_t addr) {
    asm volatile("ldmatrix.sync.aligned.m8n8.x2.shared.b16 {%0,%1}, [%2];"
                 : "=r"(r[0]), "=r"(r[1]) : "r"(addr));
}
__device__ __forceinline__ void mma_bf16(float* c, const uint32_t* a, const uint32_t* b) {
    asm volatile(
        "mma.sync.aligned.m16n8k16.row.col.f32.bf16.bf16.f32 "
        "{%0,%1,%2,%3}, {%4,%5,%6,%7}, {%8,%9}, {%0,%1,%2,%3};"
        : "+f"(c[0]), "+f"(c[1]), "+f"(c[2]), "+f"(c[3])
        : "r"(a[0]), "r"(a[1]), "r"(a[2]), "r"(a[3]), "r"(b[0]), "r"(b[1]));
}

// ---------------------------------------------------------------------------
// fp32 -> bf16 hi/lo split (elementwise, float4 granularity)
// ---------------------------------------------------------------------------
__global__ void split_bf16(const float* __restrict__ in,
                           __nv_bfloat16* __restrict__ hi,
                           __nv_bfloat16* __restrict__ lo, int n4) {
    int i = blockIdx.x * blockDim.x + threadIdx.x;
    if (i >= n4) return;
    float4 v = ((const float4*)in)[i];
    __nv_bfloat16 hx = __float2bfloat16(v.x), hy = __float2bfloat16(v.y);
    __nv_bfloat16 hz = __float2bfloat16(v.z), hw = __float2bfloat16(v.w);
    __nv_bfloat16 lx = __float2bfloat16(v.x - __bfloat162float(hx));
    __nv_bfloat16 ly = __float2bfloat16(v.y - __bfloat162float(hy));
    __nv_bfloat16 lz = __float2bfloat16(v.z - __bfloat162float(hz));
    __nv_bfloat16 lw = __float2bfloat16(v.w - __bfloat162float(hw));
    ((__nv_bfloat162*)hi)[i * 2]     = __nv_bfloat162(hx, hy);
    ((__nv_bfloat162*)hi)[i * 2 + 1] = __nv_bfloat162(hz, hw);
    ((__nv_bfloat162*)lo)[i * 2]     = __nv_bfloat162(lx, ly);
    ((__nv_bfloat162*)lo)[i * 2 + 1] = __nv_bfloat162(lz, lw);
}

// ---------------------------------------------------------------------------
// Tensor-core GEMM via mma.sync: C[M,N] = (Ah+Al)[M,K] @ (Bh+Bl)[N,K]^T
// 128x128 CTA tile, 256 threads = 2x4 warps (64x32 warp tile), K-chunk 32.
// Double-buffered cp.async stages. 3 MMAs per frag-pair (hh, hl, lh).
// Dyn smem: 2 stages x 4 arrays x 8KB = 64KB.
// ---------------------------------------------------------------------------
#define STAGE_BYTES 32768
#define GEMM_SMEM   (2 * STAGE_BYTES)
// per-stage offsets
#define OFF_AH 0
#define OFF_AL 8192
#define OFF_BH 16384
#define OFF_BL 24576

__device__ __forceinline__ void load_stage(uint32_t sbase,
                                           const __nv_bfloat16* Ah, const __nv_bfloat16* Al,
                                           const __nv_bfloat16* Bh, const __nv_bfloat16* Bl,
                                           int K, int bm, int bn, int k0, int tid) {
    // 512 16B-chunks per array; 256 threads -> 2 per array per thread.
#pragma unroll
    for (int i = 0; i < 2; i++) {
        int c = tid * 2 + i;          // 0..511
        int row = c >> 2;             // 0..127
        int cc = c & 3;               // 16B chunk within 64B row
        size_t goA = (size_t)(bm + row) * K + k0 + cc * 8;
        size_t goB = (size_t)(bn + row) * K + k0 + cc * 8;
        cp_async16(sbase + OFF_AH + c * 16, Ah + goA);
        cp_async16(sbase + OFF_AL + c * 16, Al + goA);
        cp_async16(sbase + OFF_BH + c * 16, Bh + goB);
        cp_async16(sbase + OFF_BL + c * 16, Bl + goB);
    }
}

__global__ __launch_bounds__(256) void gemm_mma(const __nv_bfloat16* __restrict__ Ah,
                                                const __nv_bfloat16* __restrict__ Al,
                                                const __nv_bfloat16* __restrict__ Bh,
                                                const __nv_bfloat16* __restrict__ Bl,
                                                float* __restrict__ C,
                                                int Ndim, int Kdim) {
    extern __shared__ char smem[];
    const uint32_t sb = smem_u32(smem);
    const int tid = threadIdx.x;
    const int wid = tid >> 5, lane = tid & 31;
    const int wm = wid >> 2;          // 0..1
    const int wn = wid & 3;           // 0..3
    const int bm = blockIdx.y * 128, bn = blockIdx.x * 128;

    float acc[4][4][4];               // [mf][nf][reg]
#pragma unroll
    for (int a = 0; a < 4; a++)
#pragma unroll
        for (int b = 0; b < 4; b++)
#pragma unroll
            for (int r = 0; r < 4; r++) acc[a][b][r] = 0.0f;

    // ldmatrix lane-address components (row-major tiles, 64B rows)
    const int a_row_base = wm * 64 + (lane & 15);       // + mf*16
    const int a_half = (lane >> 4) * 16;                // byte offset of 8-elem half
    const int b_row_base = wn * 32 + (lane & 7);        // + nf*8
    const int b_half = ((lane >> 3) & 1) * 16;          // lanes 8-15 take k+8 half

    const int nch = Kdim >> 5;
    load_stage(sb, Ah, Al, Bh, Bl, Kdim, bm, bn, 0, tid);
    asm volatile("cp.async.commit_group;");

    for (int c = 0; c < nch; c++) {
        if (c + 1 < nch) {
            load_stage(sb + ((c + 1) & 1) * STAGE_BYTES, Ah, Al, Bh, Bl,
                       Kdim, bm, bn, (c + 1) * 32, tid);
            asm volatile("cp.async.commit_group;");
            asm volatile("cp.async.wait_group 1;");
        } else {
            asm volatile("cp.async.wait_group 0;");
        }
        __syncthreads();

        const uint32_t st = sb + (c & 1) * STAGE_BYTES;
#pragma unroll
        for (int ks = 0; ks < 2; ks++) {
            // B fragments for this k16 (4 n-frags, hi+lo)
            uint32_t bh[4][2], bl[4][2];
#pragma unroll
            for (int nf = 0; nf < 4; nf++) {
                uint32_t baddr = st + (b_row_base + nf * 8) * 64 + ks * 32 + b_half;
                ldsm_x2(bh[nf], baddr + OFF_BH);
                ldsm_x2(bl[nf], baddr + OFF_BL);
            }
#pragma unroll
            for (int mf = 0; mf < 4; mf++) {
                uint32_t aaddr = st + (a_row_base + mf * 16) * 64 + ks * 32 + a_half;
                uint32_t ah[4], al[4];
                ldsm_x4(ah, aaddr + OFF_AH);
                ldsm_x4(al, aaddr + OFF_AL);
#pragma unroll
                for (int nf = 0; nf < 4; nf++) {
                    mma_bf16(acc[mf][nf], ah, bh[nf]);
                    mma_bf16(acc[mf][nf], ah, bl[nf]);
                    mma_bf16(acc[mf][nf], al, bh[nf]);
                }
            }
        }
        __syncthreads();
    }

    // epilogue: each thread owns rows (t/4, t/4+8) and cols 2*(t%4)+{0,1} per frag
    const int r0 = bm + wm * 64 + (lane >> 2);
    const int c0 = bn + wn * 32 + (lane & 3) * 2;
#pragma unroll
    for (int mf = 0; mf < 4; mf++) {
#pragma unroll
        for (int nf = 0; nf < 4; nf++) {
            float* p0 = C + (size_t)(r0 + mf * 16) * Ndim + c0 + nf * 8;
            float* p1 = p0 + 8 * Ndim;
            *(float2*)p0 = make_float2(acc[mf][nf][0], acc[mf][nf][1]);
            *(float2*)p1 = make_float2(acc[mf][nf][2], acc[mf][nf][3]);
        }
    }
}

// ---------------------------------------------------------------------------
// RoPE in-place on the Q and K thirds of g_qkv (unchanged, passed round 1)
// ---------------------------------------------------------------------------
__global__ void rope_kernel(float* __restrict__ qkv, const int* __restrict__ pos_arr) {
    int idx = blockIdx.x * blockDim.x + threadIdx.x;
    const int total = MROWS * NH * (HD / 2);
    if (idx >= total) return;
    int j = idx & 31;
    int h = (idx >> 5) & (NH - 1);
    int m = idx >> 9;
    int s = m & (S_LEN - 1);
    int p = pos_arr[s];

    float freq = powf(10000.0f, (float)j * (1.0f / 32.0f));
    float inv = 1.0f / freq;
    float ang = (float)p * inv;
    float sn, cs;
    sincosf(ang, &sn, &cs);

    float* base = qkv + (size_t)m * N3 + h * HD + 2 * j;
    float q0 = base[0], q1 = base[1];
    base[0] = q0 * cs - q1 * sn;
    base[1] = q0 * sn + q1 * cs;
    float k0 = base[DMODEL], k1 = base[DMODEL + 1];
    base[DMODEL]     = k0 * cs - k1 * sn;
    base[DMODEL + 1] = k0 * sn + k1 * cs;
}

// ---------------------------------------------------------------------------
// Causal attention, online softmax, fp32 (unchanged, passed round 1)
// ---------------------------------------------------------------------------
#define QTILE 128
#define KTILE 32

__global__ __launch_bounds__(128) void attn_kernel(const float* __restrict__ qkv,
                                                   float* __restrict__ ctx) {
    const int qt = blockIdx.x;
    const int bh = blockIdx.y;
    const int b = bh >> 4;
    const int h = bh & 15;
    const int tid = threadIdx.x;
    const int sq = qt * QTILE + tid;

    const float* base = qkv + (size_t)b * S_LEN * N3 + h * HD;

    float4 q[16];
    const float4* qrow = (const float4*)(base + (size_t)sq * N3);
#pragma unroll
    for (int i = 0; i < 16; i++) q[i] = qrow[i];

    float4 o[16];
#pragma unroll
    for (int i = 0; i < 16; i++) o[i] = make_float4(0.f, 0.f, 0.f, 0.f);
    float mx = -1e30f, lsum = 0.0f;

    __shared__ float Ks[KTILE * HD];
    __shared__ float Vs[KTILE * HD];

    const int nkt = qt * (QTILE / KTILE) + (QTILE / KTILE);

    for (int kt = 0; kt < nkt; kt++) {
        const int k0 = kt * KTILE;
        __syncthreads();
#pragma unroll
        for (int c = tid; c < KTILE * HD / 4; c += 128) {
            int j = c >> 4;
            int d4 = c & 15;
            const float* krow = base + (size_t)(k0 + j) * N3;
            ((float4*)Ks)[c] = ((const float4*)(krow + DMODEL))[d4];
            ((float4*)Vs)[c] = ((const float4*)(krow + 2 * DMODEL))[d4];
        }
        __syncthreads();

        float sc[KTILE];
        float tmax = -1e30f;
#pragma unroll
        for (int j = 0; j < KTILE; j++) {
            const float4* kr = (const float4*)(Ks + j * HD);
            float s0 = 0.f, s1 = 0.f;
#pragma unroll
            for (int i = 0; i < 16; i += 2) {
                float4 kv0 = kr[i];
                float4 kv1 = kr[i + 1];
                s0 += q[i].x * kv0.x + q[i].y * kv0.y + q[i].z * kv0.z + q[i].w * kv0.w;
                s1 += q[i + 1].x * kv1.x + q[i + 1].y * kv1.y + q[i + 1].z * kv1.z + q[i + 1].w * kv1.w;
            }
            float s = (s0 + s1) * 0.125f;
            if (k0 + j > sq) s = -1e30f;
            sc[j] = s;
            tmax = fmaxf(tmax, s);
        }

        float mnew = fmaxf(mx, tmax);
        float corr = __expf(mx - mnew);
        lsum *= corr;
#pragma unroll
        for (int i = 0; i < 16; i++) {
            o[i].x *= corr; o[i].y *= corr; o[i].z *= corr; o[i].w *= corr;
        }
#pragma unroll
        for (int j = 0; j < KTILE; j++) {
            float p = __expf(sc[j] - mnew);
            lsum += p;
            const float4* vr = (const float4*)(Vs + j * HD);
#pragma unroll
            for (int i = 0; i < 16; i++) {
                float4 vv = vr[i];
                o[i].x += p * vv.x; o[i].y += p * vv.y;
                o[i].z += p * vv.z; o[i].w += p * vv.w;
            }
        }
        mx = mnew;
    }

    const float invl = 1.0f / lsum;
    float* crow = ctx + ((size_t)(b * S_LEN + sq)) * DMODEL + h * HD;
#pragma unroll
    for (int i = 0; i < 16; i++) {
        ((float4*)crow)[i] = make_float4(o[i].x * invl, o[i].y * invl,
                                         o[i].z * invl, o[i].w * invl);
    }
}

// ---------------------------------------------------------------------------
// Launch: splits -> QKV GEMM (mma) -> RoPE -> attention -> splits -> O GEMM
// ---------------------------------------------------------------------------
extern "C" void kernel_launch(void* const* d_in, const int* in_sizes, int n_in,
                              void* d_out, int out_size) {
    const float* x     = (const float*)d_in[0];   // [4,2048,1024]
    const int*   pos   = (const int*)d_in[1];     // [2048]
    const float* qkv_w = (const float*)d_in[2];   // [3072,1024]
    const float* o_w   = (const float*)d_in[3];   // [1024,1024]
    float* out = (float*)d_out;                   // [4,2048,1024]

    float *qkv_s = nullptr, *ctx_s = nullptr;
    __nv_bfloat16 *ah = nullptr, *al = nullptr, *bh = nullptr, *bl = nullptr;
    cudaGetSymbolAddress((void**)&qkv_s, g_qkv);
    cudaGetSymbolAddress((void**)&ctx_s, g_ctx);
    cudaGetSymbolAddress((void**)&ah, g_ah);
    cudaGetSymbolAddress((void**)&al, g_al);
    cudaGetSymbolAddress((void**)&bh, g_bh);
    cudaGetSymbolAddress((void**)&bl, g_bl);

    cudaFuncSetAttribute(gemm_mma, cudaFuncAttributeMaxDynamicSharedMemorySize, GEMM_SMEM);

    // 1) split x and qkv_w into bf16 hi/lo
    {
        int n4 = MROWS * DMODEL / 4;
        split_bf16<<<(n4 + 255) / 256, 256>>>(x, ah, al, n4);
        n4 = N3 * DMODEL / 4;
        split_bf16<<<(n4 + 255) / 256, 256>>>(qkv_w, bh, bl, n4);
    }
    // 2) QKV projection on tensor cores: [8192,3072]
    {
        dim3 grid(N3 / 128, MROWS / 128);
        gemm_mma<<<grid, 256, GEMM_SMEM>>>(ah, al, bh, bl, qkv_s, N3, DMODEL);
    }
    // 3) RoPE on q,k
    {
        int total = MROWS * NH * (HD / 2);
        rope_kernel<<<(total + 255) / 256, 256>>>(qkv_s, pos);
    }
    // 4) causal attention
    {
        dim3 grid(S_LEN / QTILE, BATCH * NH);
        attn_kernel<<<grid, 128>>>(qkv_s, ctx_s);
    }
    // 5) split ctx and o_w
    {
        int n4 = MROWS * DMODEL / 4;
        split_bf16<<<(n4 + 255) / 256, 256>>>(ctx_s, ah, al, n4);
        n4 = DMODEL * DMODEL / 4;
        split_bf16<<<(n4 + 255) / 256, 256>>>(o_w, bh, bl, n4);
    }
    // 6) output projection on tensor cores: [8192,1024]
    {
        dim3 grid(DMODEL / 128, MROWS / 128);
        gemm_mma<<<grid, 256, GEMM_SMEM>>>(ah, al, bh, bl, out, DMODEL, DMODEL);
    }
}

// round 5
// speedup vs baseline: 3.7215x; 2.9899x over previous
#include <cuda_runtime.h>
#include <cuda_bf16.h>
#include <math.h>
#include <stdint.h>

// Problem constants
#define S_LEN  2048
#define DMODEL 1024
#define NH     16
#define HD     64
#define BATCH  4
#define MROWS  (BATCH * S_LEN)   // 8192
#define N3     (3 * DMODEL)      // 3072

// Scratch (no allocation allowed -> device globals)
__device__ float g_qkv[(size_t)MROWS * N3];      // [m, 3*DMODEL] fp32 (rope applied)
__device__ float g_ctx[(size_t)MROWS * DMODEL];  // [m, DMODEL]
__device__ __nv_bfloat16 g_ah[(size_t)MROWS * DMODEL];  // GEMM A hi (x or ctx)
__device__ __nv_bfloat16 g_al[(size_t)MROWS * DMODEL];  // GEMM A lo
__device__ __nv_bfloat16 g_bh[(size_t)N3 * DMODEL];     // GEMM W hi
__device__ __nv_bfloat16 g_bl[(size_t)N3 * DMODEL];     // GEMM W lo
__device__ __nv_bfloat16 g_qh[(size_t)MROWS * N3];      // qkv hi (post-rope)
__device__ __nv_bfloat16 g_ql[(size_t)MROWS * N3];      // qkv lo

// ---------------------------------------------------------------------------
// PTX helpers (portable sm_80+ only)
// ---------------------------------------------------------------------------
__device__ __forceinline__ uint32_t smem_u32(const void* p) {
    uint32_t a;
    asm("{ .reg .u64 t; cvta.to.shared.u64 t, %1; cvt.u32.u64 %0, t; }" : "=r"(a) : "l"(p));
    return a;
}
__device__ __forceinline__ void cp_async16(uint32_t saddr, const void* gaddr) {
    asm volatile("cp.async.cg.shared.global [%0], [%1], 16;" :: "r"(saddr), "l"(gaddr));
}
__device__ __forceinline__ void ldsm_x4(uint32_t* r, uint32_t addr) {
    asm volatile("ldmatrix.sync.aligned.m8n8.x4.shared.b16 {%0,%1,%2,%3}, [%4];"
                 : "=r"(r[0]), "=r"(r[1]), "=r"(r[2]), "=r"(r[3]) : "r"(addr));
}
__device__ __forceinline__ void ldsm_x2(uint32_t* r, uint32_t addr) {
    asm volatile("ldmatrix.sync.aligned.m8n8.x2.shared.b16 {%0,%1}, [%2];"
                 : "=r"(r[0]), "=r"(r[1]) : "r"(addr));
}
__device__ __forceinline__ void ldsm_x2_t(uint32_t* r, uint32_t addr) {
    asm volatile("ldmatrix.sync.aligned.m8n8.x2.trans.shared.b16 {%0,%1}, [%2];"
                 : "=r"(r[0]), "=r"(r[1]) : "r"(addr));
}
__device__ __forceinline__ void mma_bf16(float* c, const uint32_t* a, const uint32_t* b) {
    asm volatile(
        "mma.sync.aligned.m16n8k16.row.col.f32.bf16.bf16.f32 "
        "{%0,%1,%2,%3}, {%4,%5,%6,%7}, {%8,%9}, {%0,%1,%2,%3};"
        : "+f"(c[0]), "+f"(c[1]), "+f"(c[2]), "+f"(c[3])
        : "r"(a[0]), "r"(a[1]), "r"(a[2]), "r"(a[3]), "r"(b[0]), "r"(b[1]));
}
__device__ __forceinline__ uint32_t pack_bf16_res(float lo, float hi, float& rlo, float& rhi) {
    __nv_bfloat16 a = __float2bfloat16(lo), b = __float2bfloat16(hi);
    rlo = lo - __bfloat162float(a);
    rhi = hi - __bfloat162float(b);
    return (uint32_t)__bfloat16_as_ushort(a) | ((uint32_t)__bfloat16_as_ushort(b) << 16);
}
__device__ __forceinline__ uint32_t pack_bf16(float lo, float hi) {
    __nv_bfloat16 a = __float2bfloat16(lo), b = __float2bfloat16(hi);
    return (uint32_t)__bfloat16_as_ushort(a) | ((uint32_t)__bfloat16_as_ushort(b) << 16);
}

// ---------------------------------------------------------------------------
// fp32 -> bf16 hi/lo split
// ---------------------------------------------------------------------------
__global__ void split_bf16(const float* __restrict__ in,
                           __nv_bfloat16* __restrict__ hi,
                           __nv_bfloat16* __restrict__ lo, int n4) {
    int i = blockIdx.x * blockDim.x + threadIdx.x;
    if (i >= n4) return;
    float4 v = ((const float4*)in)[i];
    __nv_bfloat16 hx = __float2bfloat16(v.x), hy = __float2bfloat16(v.y);
    __nv_bfloat16 hz = __float2bfloat16(v.z), hw = __float2bfloat16(v.w);
    __nv_bfloat16 lx = __float2bfloat16(v.x - __bfloat162float(hx));
    __nv_bfloat16 ly = __float2bfloat16(v.y - __bfloat162float(hy));
    __nv_bfloat16 lz = __float2bfloat16(v.z - __bfloat162float(hz));
    __nv_bfloat16 lw = __float2bfloat16(v.w - __bfloat162float(hw));
    ((__nv_bfloat162*)hi)[i * 2]     = __nv_bfloat162(hx, hy);
    ((__nv_bfloat162*)hi)[i * 2 + 1] = __nv_bfloat162(hz, hw);
    ((__nv_bfloat162*)lo)[i * 2]     = __nv_bfloat162(lx, ly);
    ((__nv_bfloat162*)lo)[i * 2 + 1] = __nv_bfloat162(lz, lw);
}

// ---------------------------------------------------------------------------
// Tensor-core GEMM (mma.sync) with swizzled smem: C = (Ah+Al) @ (Bh+Bl)^T
// 128x128 CTA tile, 256 thr, K-chunk 32, double buffered.
// Swizzle: 16B chunk index ^= (row>>1)&3  -> conflict-free ldmatrix.
// ---------------------------------------------------------------------------
#define STAGE_BYTES 32768
#define GEMM_SMEM   (2 * STAGE_BYTES)
#define OFF_AH 0
#define OFF_AL 8192
#define OFF_BH 16384
#define OFF_BL 24576

__device__ __forceinline__ void load_stage(uint32_t sbase,
                                           const __nv_bfloat16* Ah, const __nv_bfloat16* Al,
                                           const __nv_bfloat16* Bh, const __nv_bfloat16* Bl,
                                           int K, int bm, int bn, int k0, int tid) {
#pragma unroll
    for (int i = 0; i < 2; i++) {
        int c = tid * 2 + i;          // 0..511
        int row = c >> 2;             // 0..127
        int cc = c & 3;               // 16B chunk in 64B row
        uint32_t so = row * 64 + ((cc ^ ((row >> 1) & 3)) * 16);
        size_t goA = (size_t)(bm + row) * K + k0 + cc * 8;
        size_t goB = (size_t)(bn + row) * K + k0 + cc * 8;
        cp_async16(sbase + OFF_AH + so, Ah + goA);
        cp_async16(sbase + OFF_AL + so, Al + goA);
        cp_async16(sbase + OFF_BH + so, Bh + goB);
        cp_async16(sbase + OFF_BL + so, Bl + goB);
    }
}

__global__ __launch_bounds__(256) void gemm_mma(const __nv_bfloat16* __restrict__ Ah,
                                                const __nv_bfloat16* __restrict__ Al,
                                                const __nv_bfloat16* __restrict__ Bh,
                                                const __nv_bfloat16* __restrict__ Bl,
                                                float* __restrict__ C,
                                                int Ndim, int Kdim) {
    extern __shared__ char smem[];
    const uint32_t sb = smem_u32(smem);
    const int tid = threadIdx.x;
    const int wid = tid >> 5, lane = tid & 31;
    const int wm = wid >> 2;
    const int wn = wid & 3;
    const int bm = blockIdx.y * 128, bn = blockIdx.x * 128;

    float acc[4][4][4];
#pragma unroll
    for (int a = 0; a < 4; a++)
#pragma unroll
        for (int b = 0; b < 4; b++)
#pragma unroll
            for (int r = 0; r < 4; r++) acc[a][b][r] = 0.0f;

    const int a_row_base = wm * 64 + (lane & 15);
    const uint32_t axg = ((lane & 15) >> 1) & 3;
    const int b_row_base = wn * 32 + (lane & 7);
    const uint32_t bxg = ((lane & 7) >> 1) & 3;
    const uint32_t a_csel = lane >> 4;          // 0/1
    const uint32_t b_csel = (lane >> 3) & 1;    // 0/1

    const int nch = Kdim >> 5;
    load_stage(sb, Ah, Al, Bh, Bl, Kdim, bm, bn, 0, tid);
    asm volatile("cp.async.commit_group;");

    for (int c = 0; c < nch; c++) {
        if (c + 1 < nch) {
            load_stage(sb + ((c + 1) & 1) * STAGE_BYTES, Ah, Al, Bh, Bl,
                       Kdim, bm, bn, (c + 1) * 32, tid);
            asm volatile("cp.async.commit_group;");
            asm volatile("cp.async.wait_group 1;");
        } else {
            asm volatile("cp.async.wait_group 0;");
        }
        __syncthreads();

        const uint32_t st = sb + (c & 1) * STAGE_BYTES;
#pragma unroll
        for (int ks = 0; ks < 2; ks++) {
            uint32_t bh[4][2], bl[4][2];
#pragma unroll
            for (int nf = 0; nf < 4; nf++) {
                uint32_t baddr = st + (b_row_base + nf * 8) * 64 +
                                 (((ks * 2 + b_csel) ^ bxg) * 16);
                ldsm_x2(bh[nf], baddr + OFF_BH);
                ldsm_x2(bl[nf], baddr + OFF_BL);
            }
#pragma unroll
            for (int mf = 0; mf < 4; mf++) {
                uint32_t aaddr = st + (a_row_base + mf * 16) * 64 +
                                 (((ks * 2 + a_csel) ^ axg) * 16);
                uint32_t ah[4], al[4];
                ldsm_x4(ah, aaddr + OFF_AH);
                ldsm_x4(al, aaddr + OFF_AL);
#pragma unroll
                for (int nf = 0; nf < 4; nf++) {
                    mma_bf16(acc[mf][nf], ah, bh[nf]);
                    mma_bf16(acc[mf][nf], ah, bl[nf]);
                    mma_bf16(acc[mf][nf], al, bh[nf]);
                }
            }
        }
        __syncthreads();
    }

    const int r0 = bm + wm * 64 + (lane >> 2);
    const int c0 = bn + wn * 32 + (lane & 3) * 2;
#pragma unroll
    for (int mf = 0; mf < 4; mf++) {
#pragma unroll
        for (int nf = 0; nf < 4; nf++) {
            float* p0 = C + (size_t)(r0 + mf * 16) * Ndim + c0 + nf * 8;
            float* p1 = p0 + 8 * Ndim;
            *(float2*)p0 = make_float2(acc[mf][nf][0], acc[mf][nf][1]);
            *(float2*)p1 = make_float2(acc[mf][nf][2], acc[mf][nf][3]);
        }
    }
}

// ---------------------------------------------------------------------------
// RoPE in-place on Q/K thirds of g_qkv (proven)
// ---------------------------------------------------------------------------
__global__ void rope_kernel(float* __restrict__ qkv, const int* __restrict__ pos_arr) {
    int idx = blockIdx.x * blockDim.x + threadIdx.x;
    const int total = MROWS * NH * (HD / 2);
    if (idx >= total) return;
    int j = idx & 31;
    int h = (idx >> 5) & (NH - 1);
    int m = idx >> 9;
    int s = m & (S_LEN - 1);
    int p = pos_arr[s];

    float freq = powf(10000.0f, (float)j * (1.0f / 32.0f));
    float ang = (float)p * (1.0f / freq);
    float sn, cs;
    sincosf(ang, &sn, &cs);

    float* base = qkv + (size_t)m * N3 + h * HD + 2 * j;
    float q0 = base[0], q1 = base[1];
    base[0] = q0 * cs - q1 * sn;
    base[1] = q0 * sn + q1 * cs;
    float k0 = base[DMODEL], k1 = base[DMODEL + 1];
    base[DMODEL]     = k0 * cs - k1 * sn;
    base[DMODEL + 1] = k0 * sn + k1 * cs;
}

// ---------------------------------------------------------------------------
// Flash attention on mma.sync. CTA: 64 queries, 4 warps x 16 rows. KTILE 64.
// bf16 hi/lo compensated QK^T and PV (3 MMAs each). fp32 softmax state.
// smem: Qh Ql Kh Kl Vh Vl tiles 64x64 bf16 (8KB each, 48KB total),
// 128B rows, chunk swizzle ^ (row&7).
// ---------------------------------------------------------------------------
#define AQH 0
#define AQL 8192
#define AKH 16384
#define AKL 24576
#define AVH 32768
#define AVL 40960
#define ATT_SMEM 49152

__global__ __launch_bounds__(128) void attn_mma(const __nv_bfloat16* __restrict__ Qh,
                                                const __nv_bfloat16* __restrict__ Ql,
                                                float* __restrict__ ctx) {
    extern __shared__ char smem[];
    const uint32_t sb = smem_u32(smem);
    const int qt = (S_LEN / 64 - 1) - blockIdx.x;   // reversed: big CTAs first
    const int bh = blockIdx.y;
    const int b = bh >> 4, h = bh & 15;
    const int tid = threadIdx.x;
    const int wq = tid >> 5, lane = tid & 31;
    const size_t mb = (size_t)b * S_LEN;
    const int qbase = qt * 64;
    const int qoff = h * HD;
    const int koff = DMODEL + h * HD;
    const int voff = 2 * DMODEL + h * HD;
    const uint32_t axor = (uint32_t)(lane & 7);

    // stage Q tile once
#pragma unroll
    for (int i = 0; i < 4; i++) {
        int c = tid + 128 * i;
        int row = c >> 3, j = c & 7;
        uint32_t dst = sb + (uint32_t)(row * 128 + ((j ^ (row & 7)) * 16));
        size_t g = (mb + qbase + row) * (size_t)N3 + qoff + j * 8;
        cp_async16(dst + AQH, Qh + g);
        cp_async16(dst + AQL, Ql + g);
    }
    asm volatile("cp.async.commit_group;");

    float o[8][4];
#pragma unroll
    for (int nf = 0; nf < 8; nf++)
#pragma unroll
        for (int r = 0; r < 4; r++) o[nf][r] = 0.0f;
    float m0 = -1e30f, m1 = -1e30f, l0 = 0.0f, l1 = 0.0f;

    const uint32_t qrow = wq * 16 + (lane & 15);
    const int grow0 = qbase + wq * 16 + (lane >> 2);
    const int colb = (lane & 3) * 2;

    for (int kt = 0; kt <= qt; kt++) {
        // stage K/V tiles
#pragma unroll
        for (int i = 0; i < 4; i++) {
            int c = tid + 128 * i;
            int row = c >> 3, j = c & 7;
            uint32_t dst = sb + (uint32_t)(row * 128 + ((j ^ (row & 7)) * 16));
            size_t g = (mb + kt * 64 + row) * (size_t)N3 + j * 8;
            cp_async16(dst + AKH, Qh + g + koff);
            cp_async16(dst + AKL, Ql + g + koff);
            cp_async16(dst + AVH, Qh + g + voff);
            cp_async16(dst + AVL, Ql + g + voff);
        }
        asm volatile("cp.async.commit_group;");
        asm volatile("cp.async.wait_group 0;");
        __syncthreads();

        // ---- scores S = Q K^T (compensated) ----
        float s[8][4];
#pragma unroll
        for (int nf = 0; nf < 8; nf++)
#pragma unroll
            for (int r = 0; r < 4; r++) s[nf][r] = 0.0f;

#pragma unroll
        for (int ks = 0; ks < 4; ks++) {
            uint32_t qaddr = sb + qrow * 128 + (((2 * ks + (lane >> 4)) ^ axor) * 16);
            uint32_t qh4[4], ql4[4];
            ldsm_x4(qh4, qaddr + AQH);
            ldsm_x4(ql4, qaddr + AQL);
#pragma unroll
            for (int nf = 0; nf < 8; nf++) {
                uint32_t krow = nf * 8 + (lane & 7);
                uint32_t kaddr = sb + krow * 128 +
                                 (((2 * ks + ((lane >> 3) & 1)) ^ axor) * 16);
                uint32_t kbh[2], kbl[2];
                ldsm_x2(kbh, kaddr + AKH);
                ldsm_x2(kbl, kaddr + AKL);
                mma_bf16(s[nf], qh4, kbh);
                mma_bf16(s[nf], qh4, kbl);
                mma_bf16(s[nf], ql4, kbh);
            }
        }

        // ---- scale + causal mask + online softmax ----
        float mx0 = -1e30f, mx1 = -1e30f;
#pragma unroll
        for (int nf = 0; nf < 8; nf++) {
            int col = kt * 64 + nf * 8 + colb;
            float v0 = s[nf][0] * 0.125f;
            float v1 = s[nf][1] * 0.125f;
            float v2 = s[nf][2] * 0.125f;
            float v3 = s[nf][3] * 0.125f;
            if (col     > grow0)     v0 = -1e30f;
            if (col + 1 > grow0)     v1 = -1e30f;
            if (col     > grow0 + 8) v2 = -1e30f;
            if (col + 1 > grow0 + 8) v3 = -1e30f;
            s[nf][0] = v0; s[nf][1] = v1; s[nf][2] = v2; s[nf][3] = v3;
            mx0 = fmaxf(mx0, fmaxf(v0, v1));
            mx1 = fmaxf(mx1, fmaxf(v2, v3));
        }
        mx0 = fmaxf(mx0, __shfl_xor_sync(0xFFFFFFFFu, mx0, 1));
        mx0 = fmaxf(mx0, __shfl_xor_sync(0xFFFFFFFFu, mx0, 2));
        mx1 = fmaxf(mx1, __shfl_xor_sync(0xFFFFFFFFu, mx1, 1));
        mx1 = fmaxf(mx1, __shfl_xor_sync(0xFFFFFFFFu, mx1, 2));

        float mn0 = fmaxf(m0, mx0), mn1 = fmaxf(m1, mx1);
        float cr0 = __expf(m0 - mn0), cr1 = __expf(m1 - mn1);
        float rs0 = 0.0f, rs1 = 0.0f;
#pragma unroll
        for (int nf = 0; nf < 8; nf++) {
            s[nf][0] = __expf(s[nf][0] - mn0);
            s[nf][1] = __expf(s[nf][1] - mn0);
            s[nf][2] = __expf(s[nf][2] - mn1);
            s[nf][3] = __expf(s[nf][3] - mn1);
            rs0 += s[nf][0] + s[nf][1];
            rs1 += s[nf][2] + s[nf][3];
        }
        rs0 += __shfl_xor_sync(0xFFFFFFFFu, rs0, 1);
        rs0 += __shfl_xor_sync(0xFFFFFFFFu, rs0, 2);
        rs1 += __shfl_xor_sync(0xFFFFFFFFu, rs1, 1);
        rs1 += __shfl_xor_sync(0xFFFFFFFFu, rs1, 2);
        l0 = l0 * cr0 + rs0;
        l1 = l1 * cr1 + rs1;
        m0 = mn0; m1 = mn1;
#pragma unroll
        for (int nf = 0; nf < 8; nf++) {
            o[nf][0] *= cr0; o[nf][1] *= cr0;
            o[nf][2] *= cr1; o[nf][3] *= cr1;
        }

        // ---- PV: O += P V (compensated) ----
#pragma unroll
        for (int ks = 0; ks < 4; ks++) {
            uint32_t pah[4], pal[4];
            float r0a, r0b, r1a, r1b;
            pah[0] = pack_bf16_res(s[2 * ks][0],     s[2 * ks][1],     r0a, r0b);
            pal[0] = pack_bf16(r0a, r0b);
            pah[1] = pack_bf16_res(s[2 * ks][2],     s[2 * ks][3],     r1a, r1b);
            pal[1] = pack_bf16(r1a, r1b);
            pah[2] = pack_bf16_res(s[2 * ks + 1][0], s[2 * ks + 1][1], r0a, r0b);
            pal[2] = pack_bf16(r0a, r0b);
            pah[3] = pack_bf16_res(s[2 * ks + 1][2], s[2 * ks + 1][3], r1a, r1b);
            pal[3] = pack_bf16(r1a, r1b);

            uint32_t vrow = ks * 16 + (lane & 15);
#pragma unroll
            for (int nf = 0; nf < 8; nf++) {
                uint32_t vaddr = sb + vrow * 128 + (((uint32_t)nf ^ axor) * 16);
                uint32_t vbh[2], vbl[2];
                ldsm_x2_t(vbh, vaddr + AVH);
                ldsm_x2_t(vbl, vaddr + AVL);
                mma_bf16(o[nf], pah, vbh);
                mma_bf16(o[nf], pal, vbh);
                mma_bf16(o[nf], pah, vbl);
            }
        }
        __syncthreads();   // V reads done before next tile's cp.async overwrites
    }

    const float il0 = 1.0f / l0, il1 = 1.0f / l1;
    float* cr = ctx + (mb + qbase + wq * 16 + (lane >> 2)) * DMODEL + h * HD + colb;
    float* cr8 = cr + 8 * DMODEL;
#pragma unroll
    for (int nf = 0; nf < 8; nf++) {
        *(float2*)(cr  + nf * 8) = make_float2(o[nf][0] * il0, o[nf][1] * il0);
        *(float2*)(cr8 + nf * 8) = make_float2(o[nf][2] * il1, o[nf][3] * il1);
    }
}

// ---------------------------------------------------------------------------
// Launch
// ---------------------------------------------------------------------------
extern "C" void kernel_launch(void* const* d_in, const int* in_sizes, int n_in,
                              void* d_out, int out_size) {
    const float* x     = (const float*)d_in[0];   // [4,2048,1024]
    const int*   pos   = (const int*)d_in[1];     // [2048]
    const float* qkv_w = (const float*)d_in[2];   // [3072,1024]
    const float* o_w   = (const float*)d_in[3];   // [1024,1024]
    float* out = (float*)d_out;                   // [4,2048,1024]

    float *qkv_s = nullptr, *ctx_s = nullptr;
    __nv_bfloat16 *ah = nullptr, *al = nullptr, *bh = nullptr, *bl = nullptr;
    __nv_bfloat16 *qh = nullptr, *ql = nullptr;
    cudaGetSymbolAddress((void**)&qkv_s, g_qkv);
    cudaGetSymbolAddress((void**)&ctx_s, g_ctx);
    cudaGetSymbolAddress((void**)&ah, g_ah);
    cudaGetSymbolAddress((void**)&al, g_al);
    cudaGetSymbolAddress((void**)&bh, g_bh);
    cudaGetSymbolAddress((void**)&bl, g_bl);
    cudaGetSymbolAddress((void**)&qh, g_qh);
    cudaGetSymbolAddress((void**)&ql, g_ql);

    cudaFuncSetAttribute(gemm_mma, cudaFuncAttributeMaxDynamicSharedMemorySize, GEMM_SMEM);
    cudaFuncSetAttribute(attn_mma, cudaFuncAttributeMaxDynamicSharedMemorySize, ATT_SMEM);

    // 1) split x, qkv_w
    {
        int n4 = MROWS * DMODEL / 4;
        split_bf16<<<(n4 + 255) / 256, 256>>>(x, ah, al, n4);
        n4 = N3 * DMODEL / 4;
        split_bf16<<<(n4 + 255) / 256, 256>>>(qkv_w, bh, bl, n4);
    }
    // 2) QKV projection (tensor cores)
    {
        dim3 grid(N3 / 128, MROWS / 128);
        gemm_mma<<<grid, 256, GEMM_SMEM>>>(ah, al, bh, bl, qkv_s, N3, DMODEL);
    }
    // 3) RoPE
    {
        int total = MROWS * NH * (HD / 2);
        rope_kernel<<<(total + 255) / 256, 256>>>(qkv_s, pos);
    }
    // 4) split whole qkv -> bf16 hi/lo for attention
    {
        int n4 = MROWS * N3 / 4;
        split_bf16<<<(n4 + 255) / 256, 256>>>(qkv_s, qh, ql, n4);
    }
    // 5) flash attention (tensor cores)
    {
        dim3 grid(S_LEN / 64, BATCH * NH);
        attn_mma<<<grid, 128, ATT_SMEM>>>(qh, ql, ctx_s);
    }
    // 6) split ctx, o_w
    {
        int n4 = MROWS * DMODEL / 4;
        split_bf16<<<(n4 + 255) / 256, 256>>>(ctx_s, ah, al, n4);
        n4 = DMODEL * DMODEL / 4;
        split_bf16<<<(n4 + 255) / 256, 256>>>(o_w, bh, bl, n4);
    }
    // 7) output projection (tensor cores)
    {
        dim3 grid(DMODEL / 128, MROWS / 128);
        gemm_mma<<<grid, 256, GEMM_SMEM>>>(ah, al, bh, bl, out, DMODEL, DMODEL);
    }
}